// round 1
// baseline (speedup 1.0000x reference)
#include <cuda_runtime.h>
#include <cuda_bf16.h>
#include <cstdint>

// ---------------------------------------------------------------------------
// EarlyFusionGRU: two biGRUs (B=256, T=512, H=128) + fusion MLP + 2 heads.
// Backward direction of each biGRU contributes only its FIRST step (hb_seq[0]),
// i.e. one GRU step from h0=0 on x[:, T-1]. Only forward GRUs run 512 steps.
// ---------------------------------------------------------------------------

#define B 256
#define T 512
#define H 128
#define G3 384   // 3*H

static __device__ float d_pre_g[(size_t)B * T * G3];   // fwd input projections (g net)
static __device__ float d_pre_a[(size_t)B * T * G3];   // fwd input projections (a net)
static __device__ float d_WiT[2][64 * G3];             // transposed+padded fwd input weights
static __device__ float d_hcat[(size_t)B * 512];       // [hg_f | hg_b | ha_f | ha_b]

__device__ __forceinline__ float sigmoidf_(float x) { return 1.0f / (1.0f + expf(-x)); }

// ---- transpose fwd input weights into [k][j] layout, zero-pad k to 64 ------
__global__ void tr_kernel(const float* __restrict__ g_wif, const float* __restrict__ a_wif) {
    int net = blockIdx.x;
    const float* Wi = net ? a_wif : g_wif;
    int I = net ? 64 : 63;
    int j = threadIdx.x;  // 0..383
    for (int k = 0; k < 64; k++)
        d_WiT[net][k * G3 + j] = (k < I) ? Wi[j * I + k] : 0.0f;
}

// ---- input projection: pre[t][b][j] = sum_k x[b][t][k] * WiT[k][j] + bi[j] --
__global__ __launch_bounds__(384) void proj_kernel(
    const float* __restrict__ g_x, const float* __restrict__ a_x,
    const float* __restrict__ g_bi, const float* __restrict__ a_bi) {
    int t = blockIdx.x;
    int b0 = blockIdx.y * 16;
    int net = blockIdx.z;
    const float* x = net ? a_x : g_x;
    int I = net ? 64 : 63;
    float* pre = net ? d_pre_a : d_pre_g;
    const float* bi = net ? a_bi : g_bi;

    __shared__ __align__(16) float xs[64][16];  // [k][b]
    int tid = threadIdx.x;
    for (int idx = tid; idx < 1024; idx += 384) {
        int b = idx >> 6, k = idx & 63;
        float v = 0.0f;
        if (k < I) v = x[(size_t)(b0 + b) * (T * I) + (size_t)t * I + k];
        xs[k][b] = v;
    }
    __syncthreads();

    int j = tid;
    float bj = bi[j];
    float acc[16];
#pragma unroll
    for (int b = 0; b < 16; b++) acc[b] = bj;

    const float* wt = d_WiT[net];
#pragma unroll 8
    for (int k = 0; k < 64; k++) {
        float w = wt[k * G3 + j];
        const float4* xr = (const float4*)&xs[k][0];
        float4 x0 = xr[0], x1 = xr[1], x2 = xr[2], x3 = xr[3];
        acc[0]  += w * x0.x; acc[1]  += w * x0.y; acc[2]  += w * x0.z; acc[3]  += w * x0.w;
        acc[4]  += w * x1.x; acc[5]  += w * x1.y; acc[6]  += w * x1.z; acc[7]  += w * x1.w;
        acc[8]  += w * x2.x; acc[9]  += w * x2.y; acc[10] += w * x2.z; acc[11] += w * x2.w;
        acc[12] += w * x3.x; acc[13] += w * x3.y; acc[14] += w * x3.z; acc[15] += w * x3.w;
    }
    float* orow = pre + ((size_t)t * B + b0) * G3 + j;
#pragma unroll
    for (int b = 0; b < 16; b++) orow[(size_t)b * G3] = acc[b];
}

// ---- forward GRU recurrence: Wh rows register-resident, h in smem ----------
__global__ __launch_bounds__(384, 1) void rec_kernel(
    const float* __restrict__ g_wh, const float* __restrict__ g_bh,
    const float* __restrict__ a_wh, const float* __restrict__ a_bh) {
    int net = blockIdx.y;
    int b0 = blockIdx.x * 4;
    const float* pre = net ? d_pre_a : d_pre_g;
    const float* Wh  = net ? a_wh : g_wh;
    const float* bh  = net ? a_bh : g_bh;
    int j = threadIdx.x;  // gate row 0..383

    float w[128];
#pragma unroll
    for (int k = 0; k < 128; k++) w[k] = Wh[(size_t)j * 128 + k];
    float bhj = bh[j];

    __shared__ float4 hsh[128];          // h[k] for 4 batch rows
    __shared__ float  gsh[384][4];       // gate pre-activations
    __shared__ float  xnsh[128][4];      // x-part of n gate (kept separate)

    if (j < 128) hsh[j] = make_float4(0.f, 0.f, 0.f, 0.f);
    __syncthreads();

    for (int t = 0; t < T; t++) {
        const float* prow = pre + ((size_t)t * B + b0) * G3 + j;
        float xp0 = prow[0], xp1 = prow[G3], xp2 = prow[2 * G3], xp3 = prow[3 * G3];

        float a0 = bhj, a1 = bhj, a2 = bhj, a3 = bhj;
#pragma unroll
        for (int k = 0; k < 128; k++) {
            float4 h = hsh[k];
            float wk = w[k];
            a0 += wk * h.x; a1 += wk * h.y; a2 += wk * h.z; a3 += wk * h.w;
        }
        if (j < 256) {            // r,z gates: x-part folds into the sum
            a0 += xp0; a1 += xp1; a2 += xp2; a3 += xp3;
        } else {                  // n gate: keep x-part separate (r gates h-part only)
            int u = j - 256;
            xnsh[u][0] = xp0; xnsh[u][1] = xp1; xnsh[u][2] = xp2; xnsh[u][3] = xp3;
        }
        gsh[j][0] = a0; gsh[j][1] = a1; gsh[j][2] = a2; gsh[j][3] = a3;
        __syncthreads();

        if (j < 128) {
            float* hp = (float*)&hsh[j];
#pragma unroll
            for (int b = 0; b < 4; b++) {
                float r = sigmoidf_(gsh[j][b]);
                float z = sigmoidf_(gsh[j + 128][b]);
                float n = tanhf(xnsh[j][b] + r * gsh[j + 256][b]);
                hp[b] = (1.0f - z) * n + z * hp[b];
            }
        }
        __syncthreads();
    }

    if (j < 128) {
        float4 h = hsh[j];
        int off = net ? 256 : 0;
        d_hcat[(size_t)(b0 + 0) * 512 + off + j] = h.x;
        d_hcat[(size_t)(b0 + 1) * 512 + off + j] = h.y;
        d_hcat[(size_t)(b0 + 2) * 512 + off + j] = h.z;
        d_hcat[(size_t)(b0 + 3) * 512 + off + j] = h.w;
    }
}

// ---- backward direction = ONE GRU step from h0=0 on x[:, T-1] --------------
__global__ __launch_bounds__(128) void bwd_kernel(
    const float* __restrict__ g_x, const float* __restrict__ a_x,
    const float* __restrict__ g_wib, const float* __restrict__ g_bib, const float* __restrict__ g_bhb,
    const float* __restrict__ a_wib, const float* __restrict__ a_bib, const float* __restrict__ a_bhb) {
    int b = blockIdx.x;
    int net = blockIdx.y;
    const float* x  = net ? a_x : g_x;
    int I           = net ? 64 : 63;
    const float* Wi = net ? a_wib : g_wib;
    const float* bi = net ? a_bib : g_bib;
    const float* bv = net ? a_bhb : g_bhb;

    __shared__ float xrow[64];
    int u = threadIdx.x;  // 0..127
    if (u < 64) xrow[u] = (u < I) ? x[(size_t)b * T * I + (size_t)(T - 1) * I + u] : 0.0f;
    __syncthreads();

    float s[3];
#pragma unroll
    for (int g = 0; g < 3; g++) {
        const float* wrow = Wi + (size_t)(g * 128 + u) * I;
        float acc = bi[g * 128 + u];
        for (int k = 0; k < I; k++) acc += wrow[k] * xrow[k];
        s[g] = acc;
    }
    float r = sigmoidf_(s[0] + bv[u]);
    float z = sigmoidf_(s[1] + bv[128 + u]);
    float n = tanhf(s[2] + r * bv[256 + u]);
    float hb = (1.0f - z) * n;  // + z*h0, h0 = 0

    int off = net ? 256 : 0;
    d_hcat[(size_t)b * 512 + off + 128 + u] = hb;
}

// ---- fusion MLP (512->256->128 relu) + heads (20, 30) ----------------------
__global__ __launch_bounds__(256) void mlp_kernel(
    const float* __restrict__ w1, const float* __restrict__ b1,
    const float* __restrict__ w2, const float* __restrict__ b2,
    const float* __restrict__ wm, const float* __restrict__ bm,
    const float* __restrict__ wa, const float* __restrict__ ba,
    float* __restrict__ out) {
    int b = blockIdx.x;
    __shared__ float hin[512];
    __shared__ float h1[256];
    __shared__ float h2[128];
    int t = threadIdx.x;
    hin[t]       = d_hcat[(size_t)b * 512 + t];
    hin[t + 256] = d_hcat[(size_t)b * 512 + 256 + t];
    __syncthreads();
    {
        float acc = b1[t];
        const float* wr = w1 + (size_t)t * 512;
#pragma unroll 8
        for (int k = 0; k < 512; k++) acc += wr[k] * hin[k];
        h1[t] = fmaxf(acc, 0.0f);
    }
    __syncthreads();
    if (t < 128) {
        float acc = b2[t];
        const float* wr = w2 + (size_t)t * 256;
#pragma unroll 8
        for (int k = 0; k < 256; k++) acc += wr[k] * h1[k];
        h2[t] = fmaxf(acc, 0.0f);
    }
    __syncthreads();
    if (t < 20) {
        float acc = bm[t];
        const float* wr = wm + (size_t)t * 128;
#pragma unroll 8
        for (int k = 0; k < 128; k++) acc += wr[k] * h2[k];
        out[(size_t)b * 20 + t] = acc;                       // lm
    } else if (t < 50) {
        int q = t - 20;
        float acc = ba[q];
        const float* wr = wa + (size_t)q * 128;
#pragma unroll 8
        for (int k = 0; k < 128; k++) acc += wr[k] * h2[k];
        out[5120 + (size_t)b * 30 + q] = acc;                // la (after 256*20 lm)
    }
}

extern "C" void kernel_launch(void* const* d_in, const int* in_sizes, int n_in,
                              void* d_out, int out_size) {
    const float* g_seq  = (const float*)d_in[0];
    const float* a_seq  = (const float*)d_in[1];
    const float* g_wif  = (const float*)d_in[2];
    const float* g_whf  = (const float*)d_in[3];
    const float* g_bif  = (const float*)d_in[4];
    const float* g_bhf  = (const float*)d_in[5];
    const float* g_wib  = (const float*)d_in[6];
    const float* g_bib  = (const float*)d_in[8];
    const float* g_bhb  = (const float*)d_in[9];
    const float* a_wif  = (const float*)d_in[10];
    const float* a_whf  = (const float*)d_in[11];
    const float* a_bif  = (const float*)d_in[12];
    const float* a_bhf  = (const float*)d_in[13];
    const float* a_wib  = (const float*)d_in[14];
    const float* a_bib  = (const float*)d_in[16];
    const float* a_bhb  = (const float*)d_in[17];
    const float* fuse_w1 = (const float*)d_in[18];
    const float* fuse_b1 = (const float*)d_in[19];
    const float* fuse_w2 = (const float*)d_in[20];
    const float* fuse_b2 = (const float*)d_in[21];
    const float* wm = (const float*)d_in[22];
    const float* bm = (const float*)d_in[23];
    const float* wa = (const float*)d_in[24];
    const float* ba = (const float*)d_in[25];

    tr_kernel<<<2, 384>>>(g_wif, a_wif);
    proj_kernel<<<dim3(T, B / 16, 2), 384>>>(g_seq, a_seq, g_bif, a_bif);
    bwd_kernel<<<dim3(B, 2), 128>>>(g_seq, a_seq, g_wib, g_bib, g_bhb, a_wib, a_bib, a_bhb);
    rec_kernel<<<dim3(B / 4, 2), 384>>>(g_whf, g_bhf, a_whf, a_bhf);
    mlp_kernel<<<B, 256>>>(fuse_w1, fuse_b1, fuse_w2, fuse_b2, wm, bm, wa, ba, (float*)d_out);
}

// round 2
// speedup vs baseline: 1.0566x; 1.0566x over previous
#include <cuda_runtime.h>
#include <cuda_bf16.h>
#include <cstdint>

// ---------------------------------------------------------------------------
// EarlyFusionGRU: two biGRUs (B=256, T=512, H=128) + fusion MLP + 2 heads.
// Backward direction contributes only hb_seq[0] = ONE GRU step from h0=0 on
// x[:, T-1]. Only the forward GRUs run the 512-step recurrence.
// This version uses packed fp32 FFMA2 (fma.rn.f32x2) throughout the heavy
// kernels: identical fp32 math, half the FFMA instruction count.
// ---------------------------------------------------------------------------

#define B 256
#define T 512
#define H 128
#define G3 384   // 3*H
typedef unsigned long long ull;

static __device__ float d_pre_g[(size_t)B * T * G3];   // fwd input projections (g net)
static __device__ float d_pre_a[(size_t)B * T * G3];   // fwd input projections (a net)
static __device__ ull   d_WiT2[2][64 * G3];            // transposed fwd input weights, (w,w) packed
static __device__ float d_hcat[(size_t)B * 512];       // [hg_f | hg_b | ha_f | ha_b]

__device__ __forceinline__ float sigmoidf_(float x) { return 1.0f / (1.0f + expf(-x)); }

__device__ __forceinline__ ull pk2(float lo, float hi) {
    ull r; asm("mov.b64 %0, {%1,%2};" : "=l"(r) : "f"(lo), "f"(hi)); return r;
}
__device__ __forceinline__ float2 unpk(ull v) {
    float2 f; asm("mov.b64 {%0,%1}, %2;" : "=f"(f.x), "=f"(f.y) : "l"(v)); return f;
}
// d (both lanes) += a*b, packed fp32x2
__device__ __forceinline__ void ffma2(ull& d, ull a, ull b) {
    asm("fma.rn.f32x2 %0, %1, %2, %0;" : "+l"(d) : "l"(a), "l"(b));
}
__device__ __forceinline__ ull d2l(double v) { return (ull)__double_as_longlong(v); }

// ---- transpose fwd input weights into [k][j] layout, duplicate into lanes --
__global__ void tr_kernel(const float* __restrict__ g_wif, const float* __restrict__ a_wif) {
    int net = blockIdx.x;
    const float* Wi = net ? a_wif : g_wif;
    int I = net ? 64 : 63;
    int j = threadIdx.x;  // 0..383
    for (int k = 0; k < 64; k++) {
        float w = (k < I) ? Wi[j * I + k] : 0.0f;
        d_WiT2[net][k * G3 + j] = pk2(w, w);
    }
}

// ---- input projection: pre[t][b][j] = sum_k x[b][t][k] * Wi[j][k] + bi[j] --
// Pairing over batch: each u64 accumulator holds two batch elements' sums.
__global__ __launch_bounds__(384) void proj_kernel(
    const float* __restrict__ g_x, const float* __restrict__ a_x,
    const float* __restrict__ g_bi, const float* __restrict__ a_bi) {
    int t = blockIdx.x;
    int b0 = blockIdx.y * 16;
    int net = blockIdx.z;
    const float* x = net ? a_x : g_x;
    int I = net ? 64 : 63;
    float* pre = net ? d_pre_a : d_pre_g;
    const float* bi = net ? a_bi : g_bi;

    __shared__ __align__(16) float xs[64][16];  // [k][b]
    int tid = threadIdx.x;
    for (int idx = tid; idx < 1024; idx += 384) {
        int b = idx >> 6, k = idx & 63;
        float v = 0.0f;
        if (k < I) v = x[(size_t)(b0 + b) * (T * I) + (size_t)t * I + k];
        xs[k][b] = v;
    }
    __syncthreads();

    int j = tid;
    float bj = bi[j];
    ull acc[8];
#pragma unroll
    for (int bp = 0; bp < 8; bp++) acc[bp] = pk2(bj, bj);

    const ull* wt2 = d_WiT2[net];
#pragma unroll 4
    for (int k = 0; k < 64; k++) {
        ull wd = wt2[k * G3 + j];                    // (w,w)
        const double2* xr = (const double2*)&xs[k][0];
        double2 x0 = xr[0], x1 = xr[1], x2 = xr[2], x3 = xr[3];
        ffma2(acc[0], wd, d2l(x0.x)); ffma2(acc[1], wd, d2l(x0.y));
        ffma2(acc[2], wd, d2l(x1.x)); ffma2(acc[3], wd, d2l(x1.y));
        ffma2(acc[4], wd, d2l(x2.x)); ffma2(acc[5], wd, d2l(x2.y));
        ffma2(acc[6], wd, d2l(x3.x)); ffma2(acc[7], wd, d2l(x3.y));
    }
    float* orow = pre + ((size_t)t * B + b0) * G3 + j;
#pragma unroll
    for (int bp = 0; bp < 8; bp++) {
        float2 f = unpk(acc[bp]);
        orow[(size_t)(2 * bp)     * G3] = f.x;
        orow[(size_t)(2 * bp + 1) * G3] = f.y;
    }
}

// ---- forward GRU recurrence ------------------------------------------------
// Wh row of thread j held as 64 packed (even,odd) u64 register pairs.
// Pairing over k: acc lanes = (sum over even k, sum over odd k); horizontal
// add at the end. h kept [b][k] in smem so one LDS.128 feeds two FFMA2.
__global__ __launch_bounds__(384, 1) void rec_kernel(
    const float* __restrict__ g_wh, const float* __restrict__ g_bh,
    const float* __restrict__ a_wh, const float* __restrict__ a_bh) {
    int net = blockIdx.y;
    int b0 = blockIdx.x * 4;
    const float* pre = net ? d_pre_a : d_pre_g;
    const float* Wh  = net ? a_wh : g_wh;
    const float* bh  = net ? a_bh : g_bh;
    int j = threadIdx.x;  // gate row 0..383

    ull w[64];
    const ull* wrow = (const ull*)(Wh + (size_t)j * 128);   // 512B-aligned row
#pragma unroll
    for (int i = 0; i < 64; i++) w[i] = wrow[i];
    float bhj = bh[j];

    __shared__ __align__(16) float hsh[4][128];   // h per batch row, k-contiguous
    __shared__ float gsh[4][384];                 // gate pre-activations
    __shared__ float xnsh[4][128];                // x-part of n gate

    for (int i = j; i < 512; i += 384) ((float*)hsh)[i] = 0.0f;
    __syncthreads();

    for (int t = 0; t < T; t++) {
        const float* prow = pre + ((size_t)t * B + b0) * G3 + j;
        float xp0 = prow[0], xp1 = prow[G3], xp2 = prow[2 * G3], xp3 = prow[3 * G3];

        ull a0 = pk2(bhj, 0.f), a1 = pk2(0.f, 0.f), a2 = pk2(0.f, 0.f), a3 = pk2(0.f, 0.f);
        const double2* h0p = (const double2*)hsh[0];
        const double2* h1p = (const double2*)hsh[1];
        const double2* h2p = (const double2*)hsh[2];
        const double2* h3p = (const double2*)hsh[3];
#pragma unroll
        for (int k4 = 0; k4 < 32; k4++) {
            ull w0 = w[2 * k4], w1 = w[2 * k4 + 1];
            double2 hv;
            hv = h0p[k4]; ffma2(a0, w0, d2l(hv.x)); ffma2(a0, w1, d2l(hv.y));
            hv = h1p[k4]; ffma2(a1, w0, d2l(hv.x)); ffma2(a1, w1, d2l(hv.y));
            hv = h2p[k4]; ffma2(a2, w0, d2l(hv.x)); ffma2(a2, w1, d2l(hv.y));
            hv = h3p[k4]; ffma2(a3, w0, d2l(hv.x)); ffma2(a3, w1, d2l(hv.y));
        }
        float2 f0 = unpk(a0), f1 = unpk(a1), f2 = unpk(a2), f3 = unpk(a3);
        float s0 = f0.x + f0.y, s1 = bhj + f1.x + f1.y;
        float s2 = bhj + f2.x + f2.y, s3 = bhj + f3.x + f3.y;

        if (j < 256) {            // r,z gates: fold x-part in
            s0 += xp0; s1 += xp1; s2 += xp2; s3 += xp3;
        } else {                  // n gate: x-part kept separate (r gates h-part only)
            int u = j - 256;
            xnsh[0][u] = xp0; xnsh[1][u] = xp1; xnsh[2][u] = xp2; xnsh[3][u] = xp3;
        }
        gsh[0][j] = s0; gsh[1][j] = s1; gsh[2][j] = s2; gsh[3][j] = s3;
        __syncthreads();

        if (j < 128) {
#pragma unroll
            for (int b = 0; b < 4; b++) {
                float r = sigmoidf_(gsh[b][j]);
                float z = sigmoidf_(gsh[b][j + 128]);
                float n = tanhf(xnsh[b][j] + r * gsh[b][j + 256]);
                hsh[b][j] = (1.0f - z) * n + z * hsh[b][j];
            }
        }
        __syncthreads();
    }

    if (j < 128) {
        int off = net ? 256 : 0;
#pragma unroll
        for (int b = 0; b < 4; b++)
            d_hcat[(size_t)(b0 + b) * 512 + off + j] = hsh[b][j];
    }
}

// ---- backward direction = ONE GRU step from h0=0 on x[:, T-1] --------------
__global__ __launch_bounds__(128) void bwd_kernel(
    const float* __restrict__ g_x, const float* __restrict__ a_x,
    const float* __restrict__ g_wib, const float* __restrict__ g_bib, const float* __restrict__ g_bhb,
    const float* __restrict__ a_wib, const float* __restrict__ a_bib, const float* __restrict__ a_bhb) {
    int b = blockIdx.x;
    int net = blockIdx.y;
    const float* x  = net ? a_x : g_x;
    int I           = net ? 64 : 63;
    const float* Wi = net ? a_wib : g_wib;
    const float* bi = net ? a_bib : g_bib;
    const float* bv = net ? a_bhb : g_bhb;

    __shared__ float xrow[64];
    int u = threadIdx.x;  // 0..127
    if (u < 64) xrow[u] = (u < I) ? x[(size_t)b * T * I + (size_t)(T - 1) * I + u] : 0.0f;
    __syncthreads();

    float s[3];
#pragma unroll
    for (int g = 0; g < 3; g++) {
        const float* wrow = Wi + (size_t)(g * 128 + u) * I;
        float acc = bi[g * 128 + u];
        for (int k = 0; k < I; k++) acc += wrow[k] * xrow[k];
        s[g] = acc;
    }
    float r = sigmoidf_(s[0] + bv[u]);
    float z = sigmoidf_(s[1] + bv[128 + u]);
    float n = tanhf(s[2] + r * bv[256 + u]);
    float hb = (1.0f - z) * n;  // + z*h0, h0 = 0

    int off = net ? 256 : 0;
    d_hcat[(size_t)b * 512 + off + 128 + u] = hb;
}

// ---- fusion MLP (512->256->128 relu) + heads (20, 30) ----------------------
__global__ __launch_bounds__(256) void mlp_kernel(
    const float* __restrict__ w1, const float* __restrict__ b1,
    const float* __restrict__ w2, const float* __restrict__ b2,
    const float* __restrict__ wm, const float* __restrict__ bm,
    const float* __restrict__ wa, const float* __restrict__ ba,
    float* __restrict__ out) {
    int b = blockIdx.x;
    __shared__ float hin[512];
    __shared__ float h1[256];
    __shared__ float h2[128];
    int t = threadIdx.x;
    hin[t]       = d_hcat[(size_t)b * 512 + t];
    hin[t + 256] = d_hcat[(size_t)b * 512 + 256 + t];
    __syncthreads();
    {
        float acc = b1[t];
        const float* wr = w1 + (size_t)t * 512;
#pragma unroll 8
        for (int k = 0; k < 512; k++) acc += wr[k] * hin[k];
        h1[t] = fmaxf(acc, 0.0f);
    }
    __syncthreads();
    if (t < 128) {
        float acc = b2[t];
        const float* wr = w2 + (size_t)t * 256;
#pragma unroll 8
        for (int k = 0; k < 256; k++) acc += wr[k] * h1[k];
        h2[t] = fmaxf(acc, 0.0f);
    }
    __syncthreads();
    if (t < 20) {
        float acc = bm[t];
        const float* wr = wm + (size_t)t * 128;
#pragma unroll 8
        for (int k = 0; k < 128; k++) acc += wr[k] * h2[k];
        out[(size_t)b * 20 + t] = acc;                       // lm
    } else if (t < 50) {
        int q = t - 20;
        float acc = ba[q];
        const float* wr = wa + (size_t)q * 128;
#pragma unroll 8
        for (int k = 0; k < 128; k++) acc += wr[k] * h2[k];
        out[5120 + (size_t)b * 30 + q] = acc;                // la (after 256*20 lm)
    }
}

extern "C" void kernel_launch(void* const* d_in, const int* in_sizes, int n_in,
                              void* d_out, int out_size) {
    const float* g_seq  = (const float*)d_in[0];
    const float* a_seq  = (const float*)d_in[1];
    const float* g_wif  = (const float*)d_in[2];
    const float* g_whf  = (const float*)d_in[3];
    const float* g_bif  = (const float*)d_in[4];
    const float* g_bhf  = (const float*)d_in[5];
    const float* g_wib  = (const float*)d_in[6];
    const float* g_bib  = (const float*)d_in[8];
    const float* g_bhb  = (const float*)d_in[9];
    const float* a_wif  = (const float*)d_in[10];
    const float* a_whf  = (const float*)d_in[11];
    const float* a_bif  = (const float*)d_in[12];
    const float* a_bhf  = (const float*)d_in[13];
    const float* a_wib  = (const float*)d_in[14];
    const float* a_bib  = (const float*)d_in[16];
    const float* a_bhb  = (const float*)d_in[17];
    const float* fuse_w1 = (const float*)d_in[18];
    const float* fuse_b1 = (const float*)d_in[19];
    const float* fuse_w2 = (const float*)d_in[20];
    const float* fuse_b2 = (const float*)d_in[21];
    const float* wm = (const float*)d_in[22];
    const float* bm = (const float*)d_in[23];
    const float* wa = (const float*)d_in[24];
    const float* ba = (const float*)d_in[25];

    tr_kernel<<<2, 384>>>(g_wif, a_wif);
    proj_kernel<<<dim3(T, B / 16, 2), 384>>>(g_seq, a_seq, g_bif, a_bif);
    bwd_kernel<<<dim3(B, 2), 128>>>(g_seq, a_seq, g_wib, g_bib, g_bhb, a_wib, a_bib, a_bhb);
    rec_kernel<<<dim3(B / 4, 2), 384>>>(g_whf, g_bhf, a_whf, a_bhf);
    mlp_kernel<<<B, 256>>>(fuse_w1, fuse_b1, fuse_w2, fuse_b2, wm, bm, wa, ba, (float*)d_out);
}

// round 3
// speedup vs baseline: 1.2732x; 1.2051x over previous
#include <cuda_runtime.h>
#include <cuda_bf16.h>
#include <cstdint>

// ---------------------------------------------------------------------------
// EarlyFusionGRU: two biGRUs (B=256, T=512, H=128) + fusion MLP + 2 heads.
// Backward direction contributes only hb_seq[0] = ONE GRU step from h0=0 on
// x[:, T-1]. Only the forward GRUs run the 512-step recurrence.
// fp32x2 packed FFMA2 everywhere heavy; software-pipelined LDS in the
// recurrence; tanh.approx activations spread over all 384 threads.
// ---------------------------------------------------------------------------

#define B 256
#define T 512
#define H 128
#define G3 384   // 3*H
typedef unsigned long long ull;

static __device__ float d_pre_g[(size_t)B * T * G3];   // fwd input projections (g net)
static __device__ float d_pre_a[(size_t)B * T * G3];   // fwd input projections (a net)
static __device__ ull   d_WiT2[2][64 * G3];            // transposed fwd input weights, (w,w) packed
static __device__ float d_hcat[(size_t)B * 512];       // [hg_f | hg_b | ha_f | ha_b]

__device__ __forceinline__ float sigmoidf_(float x) { return 1.0f / (1.0f + expf(-x)); }

__device__ __forceinline__ float tanh_ap(float x) {
    float y; asm("tanh.approx.f32 %0, %1;" : "=f"(y) : "f"(x)); return y;
}
__device__ __forceinline__ float sig_ap(float x) {
    return fmaf(tanh_ap(0.5f * x), 0.5f, 0.5f);
}

__device__ __forceinline__ ull pk2(float lo, float hi) {
    ull r; asm("mov.b64 %0, {%1,%2};" : "=l"(r) : "f"(lo), "f"(hi)); return r;
}
__device__ __forceinline__ float2 unpk(ull v) {
    float2 f; asm("mov.b64 {%0,%1}, %2;" : "=f"(f.x), "=f"(f.y) : "l"(v)); return f;
}
// d (both lanes) += a*b, packed fp32x2
__device__ __forceinline__ void ffma2(ull& d, ull a, ull b) {
    asm("fma.rn.f32x2 %0, %1, %2, %0;" : "+l"(d) : "l"(a), "l"(b));
}
__device__ __forceinline__ ull d2l(double v) { return (ull)__double_as_longlong(v); }

// ---- transpose fwd input weights into [k][j] layout, duplicate into lanes --
__global__ void tr_kernel(const float* __restrict__ g_wif, const float* __restrict__ a_wif) {
    int net = blockIdx.x;
    const float* Wi = net ? a_wif : g_wif;
    int I = net ? 64 : 63;
    int j = threadIdx.x;  // 0..383
    for (int k = 0; k < 64; k++) {
        float w = (k < I) ? Wi[j * I + k] : 0.0f;
        d_WiT2[net][k * G3 + j] = pk2(w, w);
    }
}

// ---- input projection: pre[t][b][j] = sum_k x[b][t][k] * Wi[j][k] + bi[j] --
// Pairing over batch: each u64 accumulator holds two batch elements' sums.
__global__ __launch_bounds__(384) void proj_kernel(
    const float* __restrict__ g_x, const float* __restrict__ a_x,
    const float* __restrict__ g_bi, const float* __restrict__ a_bi) {
    int t = blockIdx.x;
    int b0 = blockIdx.y * 16;
    int net = blockIdx.z;
    const float* x = net ? a_x : g_x;
    int I = net ? 64 : 63;
    float* pre = net ? d_pre_a : d_pre_g;
    const float* bi = net ? a_bi : g_bi;

    __shared__ __align__(16) float xs[64][16];  // [k][b]
    int tid = threadIdx.x;
    for (int idx = tid; idx < 1024; idx += 384) {
        int b = idx >> 6, k = idx & 63;
        float v = 0.0f;
        if (k < I) v = x[(size_t)(b0 + b) * (T * I) + (size_t)t * I + k];
        xs[k][b] = v;
    }
    __syncthreads();

    int j = tid;
    float bj = bi[j];
    ull acc[8];
#pragma unroll
    for (int bp = 0; bp < 8; bp++) acc[bp] = pk2(bj, bj);

    const ull* wt2 = d_WiT2[net];
    ull wd = wt2[j];                               // k = 0 prefetch
#pragma unroll 8
    for (int k = 0; k < 64; k++) {
        ull wnext = (k < 63) ? wt2[(k + 1) * G3 + j] : 0ull;
        const double2* xr = (const double2*)&xs[k][0];
        double2 x0 = xr[0], x1 = xr[1], x2 = xr[2], x3 = xr[3];
        ffma2(acc[0], wd, d2l(x0.x)); ffma2(acc[1], wd, d2l(x0.y));
        ffma2(acc[2], wd, d2l(x1.x)); ffma2(acc[3], wd, d2l(x1.y));
        ffma2(acc[4], wd, d2l(x2.x)); ffma2(acc[5], wd, d2l(x2.y));
        ffma2(acc[6], wd, d2l(x3.x)); ffma2(acc[7], wd, d2l(x3.y));
        wd = wnext;
    }
    float* orow = pre + ((size_t)t * B + b0) * G3 + j;
#pragma unroll
    for (int bp = 0; bp < 8; bp++) {
        float2 f = unpk(acc[bp]);
        orow[(size_t)(2 * bp)     * G3] = f.x;
        orow[(size_t)(2 * bp + 1) * G3] = f.y;
    }
}

// ---- forward GRU recurrence ------------------------------------------------
// Wh row of thread j held as 64 packed (even,odd) u64 register pairs.
// k-loop: 1-deep software pipeline on the h LDS loads so FFMA2s cover the
// 29-cyc LDS latency. Activations: tanh.approx, spread over all 384 threads.
__global__ __launch_bounds__(384, 1) void rec_kernel(
    const float* __restrict__ g_wh, const float* __restrict__ g_bh,
    const float* __restrict__ a_wh, const float* __restrict__ a_bh) {
    int net = blockIdx.y;
    int b0 = blockIdx.x * 4;
    const float* pre = net ? d_pre_a : d_pre_g;
    const float* Wh  = net ? a_wh : g_wh;
    const float* bh  = net ? a_bh : g_bh;
    int j = threadIdx.x;  // gate row 0..383

    ull w[64];
    const ull* wrow = (const ull*)(Wh + (size_t)j * 128);   // 512B-aligned row
#pragma unroll
    for (int i = 0; i < 64; i++) w[i] = wrow[i];
    float bhj = bh[j];

    __shared__ __align__(16) float hsh[4][128];   // h per batch row, k-contiguous
    __shared__ float gsh[4][384];                 // gate pre-activations
    __shared__ float xnsh[4][128];                // x-part of n gate

    for (int i = j; i < 512; i += 384) ((float*)hsh)[i] = 0.0f;
    __syncthreads();

    for (int t = 0; t < T; t++) {
        const float* prow = pre + ((size_t)t * B + b0) * G3 + j;
        float xp0 = prow[0], xp1 = prow[G3], xp2 = prow[2 * G3], xp3 = prow[3 * G3];

        ull a0 = pk2(0.f, 0.f), a1 = a0, a2 = a0, a3 = a0;
        const double2* h0p = (const double2*)hsh[0];
        const double2* h1p = (const double2*)hsh[1];
        const double2* h2p = (const double2*)hsh[2];
        const double2* h3p = (const double2*)hsh[3];

        double2 p0 = h0p[0], p1 = h1p[0], p2 = h2p[0], p3 = h3p[0];
#pragma unroll
        for (int k4 = 0; k4 < 32; k4++) {
            double2 q0, q1, q2, q3;
            if (k4 < 31) { q0 = h0p[k4 + 1]; q1 = h1p[k4 + 1]; q2 = h2p[k4 + 1]; q3 = h3p[k4 + 1]; }
            ull w0 = w[2 * k4], w1 = w[2 * k4 + 1];
            ffma2(a0, w0, d2l(p0.x)); ffma2(a0, w1, d2l(p0.y));
            ffma2(a1, w0, d2l(p1.x)); ffma2(a1, w1, d2l(p1.y));
            ffma2(a2, w0, d2l(p2.x)); ffma2(a2, w1, d2l(p2.y));
            ffma2(a3, w0, d2l(p3.x)); ffma2(a3, w1, d2l(p3.y));
            if (k4 < 31) { p0 = q0; p1 = q1; p2 = q2; p3 = q3; }
        }
        float2 f0 = unpk(a0), f1 = unpk(a1), f2 = unpk(a2), f3 = unpk(a3);
        float s0 = bhj + f0.x + f0.y, s1 = bhj + f1.x + f1.y;
        float s2 = bhj + f2.x + f2.y, s3 = bhj + f3.x + f3.y;

        if (j < 256) {            // r,z gates: fold x-part in
            s0 += xp0; s1 += xp1; s2 += xp2; s3 += xp3;
        } else {                  // n gate: x-part kept separate (r gates h-part only)
            int u = j - 256;
            xnsh[0][u] = xp0; xnsh[1][u] = xp1; xnsh[2][u] = xp2; xnsh[3][u] = xp3;
        }
        gsh[0][j] = s0; gsh[1][j] = s1; gsh[2][j] = s2; gsh[3][j] = s3;
        __syncthreads();

        // 512 activation entries e = b*128 + jj, spread over 384 threads:
        // thread tid does e=tid, and e=tid+384 when tid<128 (b=3, jj=tid).
        {
            int b = j >> 7, jj = j & 127;
            float r = sig_ap(gsh[b][jj]);
            float z = sig_ap(gsh[b][jj + 128]);
            float n = tanh_ap(fmaf(r, gsh[b][jj + 256], xnsh[b][jj]));
            float h = hsh[b][jj];
            float nh = n + z * (h - n);
            if (j < 128) {
                float r3 = sig_ap(gsh[3][j]);
                float z3 = sig_ap(gsh[3][j + 128]);
                float n3 = tanh_ap(fmaf(r3, gsh[3][j + 256], xnsh[3][j]));
                float h3 = hsh[3][j];
                hsh[3][j] = n3 + z3 * (h3 - n3);
            }
            hsh[b][jj] = nh;
        }
        __syncthreads();
    }

    if (j < 128) {
        int off = net ? 256 : 0;
#pragma unroll
        for (int b = 0; b < 4; b++)
            d_hcat[(size_t)(b0 + b) * 512 + off + j] = hsh[b][j];
    }
}

// ---- backward direction = ONE GRU step from h0=0 on x[:, T-1] --------------
__global__ __launch_bounds__(128) void bwd_kernel(
    const float* __restrict__ g_x, const float* __restrict__ a_x,
    const float* __restrict__ g_wib, const float* __restrict__ g_bib, const float* __restrict__ g_bhb,
    const float* __restrict__ a_wib, const float* __restrict__ a_bib, const float* __restrict__ a_bhb) {
    int b = blockIdx.x;
    int net = blockIdx.y;
    const float* x  = net ? a_x : g_x;
    int I           = net ? 64 : 63;
    const float* Wi = net ? a_wib : g_wib;
    const float* bi = net ? a_bib : g_bib;
    const float* bv = net ? a_bhb : g_bhb;

    __shared__ float xrow[64];
    int u = threadIdx.x;  // 0..127
    if (u < 64) xrow[u] = (u < I) ? x[(size_t)b * T * I + (size_t)(T - 1) * I + u] : 0.0f;
    __syncthreads();

    float s[3];
#pragma unroll
    for (int g = 0; g < 3; g++) {
        const float* wrow = Wi + (size_t)(g * 128 + u) * I;
        float acc = bi[g * 128 + u];
        for (int k = 0; k < I; k++) acc += wrow[k] * xrow[k];
        s[g] = acc;
    }
    float r = sigmoidf_(s[0] + bv[u]);
    float z = sigmoidf_(s[1] + bv[128 + u]);
    float n = tanhf(s[2] + r * bv[256 + u]);
    float hb = (1.0f - z) * n;  // + z*h0, h0 = 0

    int off = net ? 256 : 0;
    d_hcat[(size_t)b * 512 + off + 128 + u] = hb;
}

// ---- fusion MLP (512->256->128 relu) + heads (20, 30) ----------------------
__global__ __launch_bounds__(256) void mlp_kernel(
    const float* __restrict__ w1, const float* __restrict__ b1,
    const float* __restrict__ w2, const float* __restrict__ b2,
    const float* __restrict__ wm, const float* __restrict__ bm,
    const float* __restrict__ wa, const float* __restrict__ ba,
    float* __restrict__ out) {
    int b = blockIdx.x;
    __shared__ float hin[512];
    __shared__ float h1[256];
    __shared__ float h2[128];
    int t = threadIdx.x;
    hin[t]       = d_hcat[(size_t)b * 512 + t];
    hin[t + 256] = d_hcat[(size_t)b * 512 + 256 + t];
    __syncthreads();
    {
        float acc = b1[t];
        const float* wr = w1 + (size_t)t * 512;
#pragma unroll 8
        for (int k = 0; k < 512; k++) acc += wr[k] * hin[k];
        h1[t] = fmaxf(acc, 0.0f);
    }
    __syncthreads();
    if (t < 128) {
        float acc = b2[t];
        const float* wr = w2 + (size_t)t * 256;
#pragma unroll 8
        for (int k = 0; k < 256; k++) acc += wr[k] * h1[k];
        h2[t] = fmaxf(acc, 0.0f);
    }
    __syncthreads();
    if (t < 20) {
        float acc = bm[t];
        const float* wr = wm + (size_t)t * 128;
#pragma unroll 8
        for (int k = 0; k < 128; k++) acc += wr[k] * h2[k];
        out[(size_t)b * 20 + t] = acc;                       // lm
    } else if (t < 50) {
        int q = t - 20;
        float acc = ba[q];
        const float* wr = wa + (size_t)q * 128;
#pragma unroll 8
        for (int k = 0; k < 128; k++) acc += wr[k] * h2[k];
        out[5120 + (size_t)b * 30 + q] = acc;                // la (after 256*20 lm)
    }
}

extern "C" void kernel_launch(void* const* d_in, const int* in_sizes, int n_in,
                              void* d_out, int out_size) {
    const float* g_seq  = (const float*)d_in[0];
    const float* a_seq  = (const float*)d_in[1];
    const float* g_wif  = (const float*)d_in[2];
    const float* g_whf  = (const float*)d_in[3];
    const float* g_bif  = (const float*)d_in[4];
    const float* g_bhf  = (const float*)d_in[5];
    const float* g_wib  = (const float*)d_in[6];
    const float* g_bib  = (const float*)d_in[8];
    const float* g_bhb  = (const float*)d_in[9];
    const float* a_wif  = (const float*)d_in[10];
    const float* a_whf  = (const float*)d_in[11];
    const float* a_bif  = (const float*)d_in[12];
    const float* a_bhf  = (const float*)d_in[13];
    const float* a_wib  = (const float*)d_in[14];
    const float* a_bib  = (const float*)d_in[16];
    const float* a_bhb  = (const float*)d_in[17];
    const float* fuse_w1 = (const float*)d_in[18];
    const float* fuse_b1 = (const float*)d_in[19];
    const float* fuse_w2 = (const float*)d_in[20];
    const float* fuse_b2 = (const float*)d_in[21];
    const float* wm = (const float*)d_in[22];
    const float* bm = (const float*)d_in[23];
    const float* wa = (const float*)d_in[24];
    const float* ba = (const float*)d_in[25];

    tr_kernel<<<2, 384>>>(g_wif, a_wif);
    proj_kernel<<<dim3(T, B / 16, 2), 384>>>(g_seq, a_seq, g_bif, a_bif);
    bwd_kernel<<<dim3(B, 2), 128>>>(g_seq, a_seq, g_wib, g_bib, g_bhb, a_wib, a_bib, a_bhb);
    rec_kernel<<<dim3(B / 4, 2), 384>>>(g_whf, g_bhf, a_whf, a_bhf);
    mlp_kernel<<<B, 256>>>(fuse_w1, fuse_b1, fuse_w2, fuse_b2, wm, bm, wa, ba, (float*)d_out);
}

// round 5
// speedup vs baseline: 1.4559x; 1.1435x over previous
#include <cuda_runtime.h>
#include <cuda_bf16.h>
#include <cuda_fp16.h>
#include <cstdint>

// ---------------------------------------------------------------------------
// EarlyFusionGRU: two biGRUs (B=256, T=512, H=128) + fusion MLP + 2 heads.
// Backward direction contributes only hb_seq[0] = ONE GRU step from h0=0 on
// x[:, T-1]. Forward recurrence: mma.sync (HMMA) with fp16 2-term W split,
// A fragments register-resident across all 512 steps.
// ---------------------------------------------------------------------------

#define B 256
#define T 512
#define H 128
#define G3 384   // 3*H
typedef unsigned long long ull;

static __device__ float d_pre_g[(size_t)B * T * G3];   // fwd input projections (g net)
static __device__ float d_pre_a[(size_t)B * T * G3];   // fwd input projections (a net)
static __device__ float d_WiT[2][64 * G3];             // transposed+padded fwd input weights
static __device__ float d_hcat[(size_t)B * 512];       // [hg_f | hg_b | ha_f | ha_b]

__device__ __forceinline__ float sigmoidf_(float x) { return 1.0f / (1.0f + expf(-x)); }
__device__ __forceinline__ float tanh_ap(float x) {
    float y; asm("tanh.approx.f32 %0, %1;" : "=f"(y) : "f"(x)); return y;
}
__device__ __forceinline__ float sig_ap(float x) {
    return fmaf(tanh_ap(0.5f * x), 0.5f, 0.5f);
}
__device__ __forceinline__ ull pk2(float lo, float hi) {
    ull r; asm("mov.b64 %0, {%1,%2};" : "=l"(r) : "f"(lo), "f"(hi)); return r;
}
__device__ __forceinline__ float2 unpk(ull v) {
    float2 f; asm("mov.b64 {%0,%1}, %2;" : "=f"(f.x), "=f"(f.y) : "l"(v)); return f;
}
__device__ __forceinline__ void ffma2(ull& d, ull a, ull b) {
    asm("fma.rn.f32x2 %0, %1, %2, %0;" : "+l"(d) : "l"(a), "l"(b));
}
__device__ __forceinline__ ull d2l(double v) { return (ull)__double_as_longlong(v); }

__device__ __forceinline__ uint32_t pkh2(float a, float b) {
    __half2 h = __floats2half2_rn(a, b);   // .x = a (low), .y = b (high)
    return *(uint32_t*)&h;
}
// split float2 into fp16 hi-pair and fp16 lo-pair
__device__ __forceinline__ void split2(float2 v, uint32_t& hi, uint32_t& lo) {
    float hx = __half2float(__float2half_rn(v.x));
    float hy = __half2float(__float2half_rn(v.y));
    hi = pkh2(hx, hy);
    lo = pkh2(v.x - hx, v.y - hy);
}
__device__ __forceinline__ void mma16816(float* c, const uint32_t* a, uint32_t b0, uint32_t b1) {
    asm volatile(
        "mma.sync.aligned.m16n8k16.row.col.f32.f16.f16.f32 "
        "{%0,%1,%2,%3}, {%4,%5,%6,%7}, {%8,%9}, {%0,%1,%2,%3};"
        : "+f"(c[0]), "+f"(c[1]), "+f"(c[2]), "+f"(c[3])
        : "r"(a[0]), "r"(a[1]), "r"(a[2]), "r"(a[3]), "r"(b0), "r"(b1));
}

// ---- transpose fwd input weights into [k][j] layout, zero-pad k to 64 ------
__global__ void tr_kernel(const float* __restrict__ g_wif, const float* __restrict__ a_wif) {
    int net = blockIdx.x;
    const float* Wi = net ? a_wif : g_wif;
    int I = net ? 64 : 63;
    int j = threadIdx.x;  // 0..383
    for (int k = 0; k < 64; k++)
        d_WiT[net][k * G3 + j] = (k < I) ? Wi[j * I + k] : 0.0f;
}

// ---- input projection: W cached in SMEM, 4 t-steps x 32 batches per block --
__global__ __launch_bounds__(384) void proj_kernel(
    const float* __restrict__ g_x, const float* __restrict__ a_x,
    const float* __restrict__ g_bi, const float* __restrict__ a_bi) {
    extern __shared__ float sm[];
    float* ws = sm;                                   // [64*384]
    float (*xs)[32] = (float(*)[32])(sm + 24576);     // [64][32]

    int t0 = blockIdx.x * 4;
    int b0 = blockIdx.y * 32;
    int net = blockIdx.z;
    const float* x = net ? a_x : g_x;
    int I = net ? 64 : 63;
    float* pre = net ? d_pre_a : d_pre_g;
    const float* bi = net ? a_bi : g_bi;

    int j = threadIdx.x;
    const float* wt = d_WiT[net];
    for (int i = j; i < 24576; i += 384) ws[i] = wt[i];
    float bj = bi[j];

    for (int tt = 0; tt < 4; tt++) {
        int t = t0 + tt;
        __syncthreads();
        for (int idx = j; idx < 2048; idx += 384) {
            int b = idx >> 6, k = idx & 63;
            float v = 0.0f;
            if (k < I) v = x[(size_t)(b0 + b) * (T * I) + (size_t)t * I + k];
            xs[k][b] = v;
        }
        __syncthreads();

        ull acc[16];
#pragma unroll
        for (int bp = 0; bp < 16; bp++) acc[bp] = pk2(bj, bj);

#pragma unroll 4
        for (int k = 0; k < 64; k++) {
            float w = ws[k * 384 + j];
            ull wd = pk2(w, w);
            const double2* xr = (const double2*)&xs[k][0];
#pragma unroll
            for (int q = 0; q < 8; q++) {
                double2 xv = xr[q];
                ffma2(acc[2 * q],     wd, d2l(xv.x));
                ffma2(acc[2 * q + 1], wd, d2l(xv.y));
            }
        }
        float* orow = pre + ((size_t)t * B + b0) * G3 + j;
#pragma unroll
        for (int bp = 0; bp < 16; bp++) {
            float2 f = unpk(acc[bp]);
            orow[(size_t)(2 * bp)     * G3] = f.x;
            orow[(size_t)(2 * bp + 1) * G3] = f.y;
        }
    }
}

// ---- forward GRU recurrence on HMMA (mma.sync) -----------------------------
// Per step: D[384,8] = [W1|W2](384x256 fp16) @ [h16; h16](256x8).
// W fragments register-resident (8 warps x 3 m-tiles x 16 ksteps x 4 regs).
// h carried fp32 in registers; fed to MMA as single fp16 via SMEM B tile.
__global__ __launch_bounds__(256, 1) void rec_mma_kernel(
    const float* __restrict__ g_wh, const float* __restrict__ g_bh,
    const float* __restrict__ a_wh, const float* __restrict__ a_bh) {
    int net = blockIdx.y;
    int b0 = blockIdx.x * 8;
    const float* pre = net ? d_pre_a : d_pre_g;
    const float* Wh  = net ? a_wh : g_wh;
    const float* bh  = net ? a_bh : g_bh;

    int tid = threadIdx.x;
    int wid = tid >> 5;
    int lane = tid & 31;
    int qr = lane >> 2;     // groupID (row/col-of-n within frag)
    int qc = lane & 3;      // thread-in-group

    __shared__ __half Bh[8][136];      // [n(batch)][k(hidden)], padded: conflict-free
    __shared__ float  Dsh[384][10];    // gate pre-activation exchange

    // ---- build register-resident A fragments (hi at ks 0-7, lo at ks 8-15) -
    uint32_t A[3][16][4];
#pragma unroll
    for (int mt = 0; mt < 3; mt++) {
        int R = (wid * 3 + mt) * 16;
        int r0 = R + qr, r1 = r0 + 8;
        const float2* w0p = (const float2*)(Wh + (size_t)r0 * 128);
        const float2* w1p = (const float2*)(Wh + (size_t)r1 * 128);
#pragma unroll
        for (int kb = 0; kb < 8; kb++) {
            int ci = kb * 8 + qc;          // float2 index of k0 = kb*16 + qc*2
            float2 e00 = w0p[ci], e10 = w1p[ci];
            float2 e01 = w0p[ci + 4], e11 = w1p[ci + 4];
            split2(e00, A[mt][kb][0], A[mt][kb + 8][0]);
            split2(e10, A[mt][kb][1], A[mt][kb + 8][1]);
            split2(e01, A[mt][kb][2], A[mt][kb + 8][2]);
            split2(e11, A[mt][kb][3], A[mt][kb + 8][3]);
        }
    }

    // zero B tile (h0 = 0)
    for (int i = tid; i < 8 * 136 / 2; i += 256)
        ((uint32_t*)Bh)[i] = 0u;

    // activation bookkeeping: this thread owns (bb = bbase+2i, jj) for i=0..3
    int bbase = tid >> 7;          // 0 or 1
    int jj = tid & 127;
    float br = bh[jj], bz = bh[128 + jj], bn = bh[256 + jj];
    const float* xbase = pre + (size_t)(b0 + bbase) * G3 + jj;

    float h[4];
#pragma unroll
    for (int i = 0; i < 4; i++) h[i] = 0.0f;

    const __half* BhF = &Bh[0][0];
    __syncthreads();

#pragma unroll 1
    for (int t = 0; t < T; t++) {
        // prefetch x-parts for this step's activation (covered by MMA phase)
        float xr_[4], xz_[4], xn_[4];
        const float* p = xbase + (size_t)t * (B * G3);
#pragma unroll
        for (int i = 0; i < 4; i++) {
            xr_[i] = p[0]; xz_[i] = p[128]; xn_[i] = p[256];
            p += 2 * G3;
        }

        // MMA phase: D = W1@h16 + W2@h16
        float c[3][4];
#pragma unroll
        for (int mt = 0; mt < 3; mt++) { c[mt][0] = c[mt][1] = c[mt][2] = c[mt][3] = 0.0f; }
#pragma unroll
        for (int ks = 0; ks < 16; ks++) {
            int kb = ks & 7;
            int koff = qr * 136 + kb * 16 + qc * 2;
            uint32_t bf0 = *(const uint32_t*)(BhF + koff);
            uint32_t bf1 = *(const uint32_t*)(BhF + koff + 8);
#pragma unroll
            for (int mt = 0; mt < 3; mt++) mma16816(c[mt], A[mt][ks], bf0, bf1);
        }
#pragma unroll
        for (int mt = 0; mt < 3; mt++) {
            int R = (wid * 3 + mt) * 16;
            *(float2*)&Dsh[R + qr][2 * qc]     = make_float2(c[mt][0], c[mt][1]);
            *(float2*)&Dsh[R + qr + 8][2 * qc] = make_float2(c[mt][2], c[mt][3]);
        }
        __syncthreads();

        // activation phase: 4 (batch, jj) entries per thread
#pragma unroll
        for (int i = 0; i < 4; i++) {
            int bb = bbase + 2 * i;
            float r = sig_ap(xr_[i] + br + Dsh[jj][bb]);
            float z = sig_ap(xz_[i] + bz + Dsh[jj + 128][bb]);
            float n = tanh_ap(fmaf(r, bn + Dsh[jj + 256][bb], xn_[i]));
            h[i] = n + z * (h[i] - n);
            Bh[bb][jj] = __float2half_rn(h[i]);
        }
        __syncthreads();
    }

    // write final forward h
    {
        int off = net ? 256 : 0;
#pragma unroll
        for (int i = 0; i < 4; i++) {
            int bb = bbase + 2 * i;
            d_hcat[(size_t)(b0 + bb) * 512 + off + jj] = h[i];
        }
    }
}

// ---- backward direction = ONE GRU step from h0=0 on x[:, T-1] --------------
__global__ __launch_bounds__(128) void bwd_kernel(
    const float* __restrict__ g_x, const float* __restrict__ a_x,
    const float* __restrict__ g_wib, const float* __restrict__ g_bib, const float* __restrict__ g_bhb,
    const float* __restrict__ a_wib, const float* __restrict__ a_bib, const float* __restrict__ a_bhb) {
    int b = blockIdx.x;
    int net = blockIdx.y;
    const float* x  = net ? a_x : g_x;
    int I           = net ? 64 : 63;
    const float* Wi = net ? a_wib : g_wib;
    const float* bi = net ? a_bib : g_bib;
    const float* bv = net ? a_bhb : g_bhb;

    __shared__ float xrow[64];
    int u = threadIdx.x;  // 0..127
    if (u < 64) xrow[u] = (u < I) ? x[(size_t)b * T * I + (size_t)(T - 1) * I + u] : 0.0f;
    __syncthreads();

    float s[3];
#pragma unroll
    for (int g = 0; g < 3; g++) {
        const float* wrow = Wi + (size_t)(g * 128 + u) * I;
        float acc = bi[g * 128 + u];
        for (int k = 0; k < I; k++) acc += wrow[k] * xrow[k];
        s[g] = acc;
    }
    float r = sigmoidf_(s[0] + bv[u]);
    float z = sigmoidf_(s[1] + bv[128 + u]);
    float n = tanhf(s[2] + r * bv[256 + u]);
    float hb = (1.0f - z) * n;  // + z*h0, h0 = 0

    int off = net ? 256 : 0;
    d_hcat[(size_t)b * 512 + off + 128 + u] = hb;
}

// ---- fusion MLP (512->256->128 relu) + heads (20, 30) ----------------------
__global__ __launch_bounds__(256) void mlp_kernel(
    const float* __restrict__ w1, const float* __restrict__ b1,
    const float* __restrict__ w2, const float* __restrict__ b2,
    const float* __restrict__ wm, const float* __restrict__ bm,
    const float* __restrict__ wa, const float* __restrict__ ba,
    float* __restrict__ out) {
    int b = blockIdx.x;
    __shared__ float hin[512];
    __shared__ float h1[256];
    __shared__ float h2[128];
    int t = threadIdx.x;
    hin[t]       = d_hcat[(size_t)b * 512 + t];
    hin[t + 256] = d_hcat[(size_t)b * 512 + 256 + t];
    __syncthreads();
    {
        float acc = b1[t];
        const float* wr = w1 + (size_t)t * 512;
#pragma unroll 8
        for (int k = 0; k < 512; k++) acc += wr[k] * hin[k];
        h1[t] = fmaxf(acc, 0.0f);
    }
    __syncthreads();
    if (t < 128) {
        float acc = b2[t];
        const float* wr = w2 + (size_t)t * 256;
#pragma unroll 8
        for (int k = 0; k < 256; k++) acc += wr[k] * h1[k];
        h2[t] = fmaxf(acc, 0.0f);
    }
    __syncthreads();
    if (t < 20) {
        float acc = bm[t];
        const float* wr = wm + (size_t)t * 128;
#pragma unroll 8
        for (int k = 0; k < 128; k++) acc += wr[k] * h2[k];
        out[(size_t)b * 20 + t] = acc;                       // lm
    } else if (t < 50) {
        int q = t - 20;
        float acc = ba[q];
        const float* wr = wa + (size_t)q * 128;
#pragma unroll 8
        for (int k = 0; k < 128; k++) acc += wr[k] * h2[k];
        out[5120 + (size_t)b * 30 + q] = acc;                // la (after 256*20 lm)
    }
}

extern "C" void kernel_launch(void* const* d_in, const int* in_sizes, int n_in,
                              void* d_out, int out_size) {
    const float* g_seq  = (const float*)d_in[0];
    const float* a_seq  = (const float*)d_in[1];
    const float* g_wif  = (const float*)d_in[2];
    const float* g_whf  = (const float*)d_in[3];
    const float* g_bif  = (const float*)d_in[4];
    const float* g_bhf  = (const float*)d_in[5];
    const float* g_wib  = (const float*)d_in[6];
    const float* g_bib  = (const float*)d_in[8];
    const float* g_bhb  = (const float*)d_in[9];
    const float* a_wif  = (const float*)d_in[10];
    const float* a_whf  = (const float*)d_in[11];
    const float* a_bif  = (const float*)d_in[12];
    const float* a_bhf  = (const float*)d_in[13];
    const float* a_wib  = (const float*)d_in[14];
    const float* a_bib  = (const float*)d_in[16];
    const float* a_bhb  = (const float*)d_in[17];
    const float* fuse_w1 = (const float*)d_in[18];
    const float* fuse_b1 = (const float*)d_in[19];
    const float* fuse_w2 = (const float*)d_in[20];
    const float* fuse_b2 = (const float*)d_in[21];
    const float* wm = (const float*)d_in[22];
    const float* bm = (const float*)d_in[23];
    const float* wa = (const float*)d_in[24];
    const float* ba = (const float*)d_in[25];

    static int smem_set = 0;
    if (!smem_set) {
        cudaFuncSetAttribute(proj_kernel, cudaFuncAttributeMaxDynamicSharedMemorySize, 106496);
        smem_set = 1;
    }

    tr_kernel<<<2, 384>>>(g_wif, a_wif);
    proj_kernel<<<dim3(T / 4, B / 32, 2), 384, 106496>>>(g_seq, a_seq, g_bif, a_bif);
    bwd_kernel<<<dim3(B, 2), 128>>>(g_seq, a_seq, g_wib, g_bib, g_bhb, a_wib, a_bib, a_bhb);
    rec_mma_kernel<<<dim3(B / 8, 2), 256>>>(g_whf, g_bhf, a_whf, a_bhf);
    mlp_kernel<<<B, 256>>>(fuse_w1, fuse_b1, fuse_w2, fuse_b2, wm, bm, wa, ba, (float*)d_out);
}

// round 6
// speedup vs baseline: 1.6136x; 1.1083x over previous
#include <cuda_runtime.h>
#include <cuda_bf16.h>
#include <cuda_fp16.h>
#include <cstdint>

// ---------------------------------------------------------------------------
// EarlyFusionGRU: two biGRUs (B=256, T=512, H=128) + fusion MLP + 2 heads.
// Backward direction contributes only hb_seq[0] = ONE GRU step from h0=0 on
// x[:, T-1]. Forward recurrence: mma.sync (HMMA) with fp16 2-term W split.
// R6: 512 threads/CTA; the two split terms (Whi/Wlo) run on separate warps
// (8-deep MMA chains instead of 16), activation spread 2 entries/thread.
// ---------------------------------------------------------------------------

#define B 256
#define T 512
#define H 128
#define G3 384   // 3*H
typedef unsigned long long ull;

static __device__ float d_pre_g[(size_t)B * T * G3];   // fwd input projections (g net)
static __device__ float d_pre_a[(size_t)B * T * G3];   // fwd input projections (a net)
static __device__ float d_WiT[2][64 * G3];             // transposed+padded fwd input weights
static __device__ float d_hcat[(size_t)B * 512];       // [hg_f | hg_b | ha_f | ha_b]

__device__ __forceinline__ float sigmoidf_(float x) { return 1.0f / (1.0f + expf(-x)); }
__device__ __forceinline__ float tanh_ap(float x) {
    float y; asm("tanh.approx.f32 %0, %1;" : "=f"(y) : "f"(x)); return y;
}
__device__ __forceinline__ float sig_ap(float x) {
    return fmaf(tanh_ap(0.5f * x), 0.5f, 0.5f);
}
__device__ __forceinline__ ull pk2(float lo, float hi) {
    ull r; asm("mov.b64 %0, {%1,%2};" : "=l"(r) : "f"(lo), "f"(hi)); return r;
}
__device__ __forceinline__ float2 unpk(ull v) {
    float2 f; asm("mov.b64 {%0,%1}, %2;" : "=f"(f.x), "=f"(f.y) : "l"(v)); return f;
}
__device__ __forceinline__ void ffma2(ull& d, ull a, ull b) {
    asm("fma.rn.f32x2 %0, %1, %2, %0;" : "+l"(d) : "l"(a), "l"(b));
}
__device__ __forceinline__ ull d2l(double v) { return (ull)__double_as_longlong(v); }

__device__ __forceinline__ uint32_t pkh2(float a, float b) {
    __half2 h = __floats2half2_rn(a, b);
    return *(uint32_t*)&h;
}
// split float2 into fp16 hi-pair and fp16 lo-pair
__device__ __forceinline__ void split2(float2 v, uint32_t& hi, uint32_t& lo) {
    float hx = __half2float(__float2half_rn(v.x));
    float hy = __half2float(__float2half_rn(v.y));
    hi = pkh2(hx, hy);
    lo = pkh2(v.x - hx, v.y - hy);
}
__device__ __forceinline__ void mma16816(float* c, const uint32_t* a, uint32_t b0, uint32_t b1) {
    asm volatile(
        "mma.sync.aligned.m16n8k16.row.col.f32.f16.f16.f32 "
        "{%0,%1,%2,%3}, {%4,%5,%6,%7}, {%8,%9}, {%0,%1,%2,%3};"
        : "+f"(c[0]), "+f"(c[1]), "+f"(c[2]), "+f"(c[3])
        : "r"(a[0]), "r"(a[1]), "r"(a[2]), "r"(a[3]), "r"(b0), "r"(b1));
}

// ---- transpose fwd input weights into [k][j] layout, zero-pad k to 64 ------
__global__ void tr_kernel(const float* __restrict__ g_wif, const float* __restrict__ a_wif) {
    int net = blockIdx.x;
    const float* Wi = net ? a_wif : g_wif;
    int I = net ? 64 : 63;
    int j = threadIdx.x;  // 0..383
    for (int k = 0; k < 64; k++)
        d_WiT[net][k * G3 + j] = (k < I) ? Wi[j * I + k] : 0.0f;
}

// ---- input projection: W cached in SMEM, 4 t-steps x 32 batches per block --
__global__ __launch_bounds__(384) void proj_kernel(
    const float* __restrict__ g_x, const float* __restrict__ a_x,
    const float* __restrict__ g_bi, const float* __restrict__ a_bi) {
    extern __shared__ float sm[];
    float* ws = sm;                                   // [64*384]
    float (*xs)[32] = (float(*)[32])(sm + 24576);     // [64][32]

    int t0 = blockIdx.x * 4;
    int b0 = blockIdx.y * 32;
    int net = blockIdx.z;
    const float* x = net ? a_x : g_x;
    int I = net ? 64 : 63;
    float* pre = net ? d_pre_a : d_pre_g;
    const float* bi = net ? a_bi : g_bi;

    int j = threadIdx.x;
    const float* wt = d_WiT[net];
    for (int i = j; i < 24576; i += 384) ws[i] = wt[i];
    float bj = bi[j];

    for (int tt = 0; tt < 4; tt++) {
        int t = t0 + tt;
        __syncthreads();
        for (int idx = j; idx < 2048; idx += 384) {
            int b = idx >> 6, k = idx & 63;
            float v = 0.0f;
            if (k < I) v = x[(size_t)(b0 + b) * (T * I) + (size_t)t * I + k];
            xs[k][b] = v;
        }
        __syncthreads();

        ull acc[16];
#pragma unroll
        for (int bp = 0; bp < 16; bp++) acc[bp] = pk2(bj, bj);

#pragma unroll 4
        for (int k = 0; k < 64; k++) {
            float w = ws[k * 384 + j];
            ull wd = pk2(w, w);
            const double2* xr = (const double2*)&xs[k][0];
#pragma unroll
            for (int q = 0; q < 8; q++) {
                double2 xv = xr[q];
                ffma2(acc[2 * q],     wd, d2l(xv.x));
                ffma2(acc[2 * q + 1], wd, d2l(xv.y));
            }
        }
        float* orow = pre + ((size_t)t * B + b0) * G3 + j;
#pragma unroll
        for (int bp = 0; bp < 16; bp++) {
            float2 f = unpk(acc[bp]);
            orow[(size_t)(2 * bp)     * G3] = f.x;
            orow[(size_t)(2 * bp + 1) * G3] = f.y;
        }
    }
}

// ---- forward GRU recurrence on HMMA (mma.sync), split terms across warps ---
// Per step: D[384,8] = Whi@h16 + Wlo@h16. 16 warps: warp = (mgroup 0-7,
// khalf 0/1); khalf selects the split term; each warp runs 3 m-tiles with an
// 8-deep k chain. Partial sums per term exchanged via Dsh[2]; activation adds.
__global__ __launch_bounds__(512, 1) void rec_mma_kernel(
    const float* __restrict__ g_wh, const float* __restrict__ g_bh,
    const float* __restrict__ a_wh, const float* __restrict__ a_bh) {
    int net = blockIdx.y;
    int b0 = blockIdx.x * 8;
    const float* pre = net ? d_pre_a : d_pre_g;
    const float* Wh  = net ? a_wh : g_wh;
    const float* bh  = net ? a_bh : g_bh;

    int tid = threadIdx.x;
    int wid = tid >> 5;
    int lane = tid & 31;
    int qr = lane >> 2;     // groupID
    int qc = lane & 3;      // thread-in-group
    int mgroup = wid >> 1;  // 0..7 -> rows [mgroup*48, mgroup*48+48)
    int khalf = wid & 1;    // 0 = hi term, 1 = lo term

    __shared__ __half Bh[8][136];         // [n(batch)][k(hidden)], padded
    __shared__ float  Dsh[2][384][10];    // per-term gate pre-activations

    // ---- register-resident A fragments: this warp's term only --------------
    uint32_t A[3][8][4];
#pragma unroll
    for (int mt = 0; mt < 3; mt++) {
        int R = (mgroup * 3 + mt) * 16;
        int r0 = R + qr, r1 = r0 + 8;
        const float2* w0p = (const float2*)(Wh + (size_t)r0 * 128);
        const float2* w1p = (const float2*)(Wh + (size_t)r1 * 128);
#pragma unroll
        for (int kb = 0; kb < 8; kb++) {
            int ci = kb * 8 + qc;
            float2 e00 = w0p[ci], e10 = w1p[ci];
            float2 e01 = w0p[ci + 4], e11 = w1p[ci + 4];
            uint32_t hi, lo;
            split2(e00, hi, lo); A[mt][kb][0] = khalf ? lo : hi;
            split2(e10, hi, lo); A[mt][kb][1] = khalf ? lo : hi;
            split2(e01, hi, lo); A[mt][kb][2] = khalf ? lo : hi;
            split2(e11, hi, lo); A[mt][kb][3] = khalf ? lo : hi;
        }
    }

    // zero B tile (h0 = 0)
    for (int i = tid; i < 8 * 136 / 2; i += 512)
        ((uint32_t*)Bh)[i] = 0u;

    // activation bookkeeping: thread owns (bL, jj) and (bL+4, jj)
    int bL = tid >> 7;            // 0..3
    int jj = tid & 127;
    float br = bh[jj], bz = bh[128 + jj], bn = bh[256 + jj];

    float h[2];
    h[0] = 0.0f; h[1] = 0.0f;

    const __half* BhF = &Bh[0][0];
    __syncthreads();

#pragma unroll 1
    for (int t = 0; t < T; t++) {
        // prefetch x-parts (consumed after the MMA barrier)
        const float* p = pre + ((size_t)t * B + b0 + bL) * G3 + jj;
        float xr0 = p[0], xz0 = p[128], xn0 = p[256];
        const float* p2 = p + 4 * G3;
        float xr1 = p2[0], xz1 = p2[128], xn1 = p2[256];

        // MMA phase: this warp's term, 8-deep chain
        float c[3][4];
#pragma unroll
        for (int mt = 0; mt < 3; mt++) { c[mt][0] = c[mt][1] = c[mt][2] = c[mt][3] = 0.0f; }
#pragma unroll
        for (int kb = 0; kb < 8; kb++) {
            int koff = qr * 136 + kb * 16 + qc * 2;
            uint32_t bf0 = *(const uint32_t*)(BhF + koff);
            uint32_t bf1 = *(const uint32_t*)(BhF + koff + 8);
#pragma unroll
            for (int mt = 0; mt < 3; mt++) mma16816(c[mt], A[mt][kb], bf0, bf1);
        }
#pragma unroll
        for (int mt = 0; mt < 3; mt++) {
            int R = (mgroup * 3 + mt) * 16;
            *(float2*)&Dsh[khalf][R + qr][2 * qc]     = make_float2(c[mt][0], c[mt][1]);
            *(float2*)&Dsh[khalf][R + qr + 8][2 * qc] = make_float2(c[mt][2], c[mt][3]);
        }
        __syncthreads();

        // activation phase: 2 (batch, jj) entries per thread
        {
            int bb = bL;
            float dr = Dsh[0][jj][bb]       + Dsh[1][jj][bb];
            float dz = Dsh[0][jj + 128][bb] + Dsh[1][jj + 128][bb];
            float dn = Dsh[0][jj + 256][bb] + Dsh[1][jj + 256][bb];
            float r = sig_ap(xr0 + br + dr);
            float z = sig_ap(xz0 + bz + dz);
            float n = tanh_ap(fmaf(r, bn + dn, xn0));
            h[0] = n + z * (h[0] - n);
            Bh[bb][jj] = __float2half_rn(h[0]);
        }
        {
            int bb = bL + 4;
            float dr = Dsh[0][jj][bb]       + Dsh[1][jj][bb];
            float dz = Dsh[0][jj + 128][bb] + Dsh[1][jj + 128][bb];
            float dn = Dsh[0][jj + 256][bb] + Dsh[1][jj + 256][bb];
            float r = sig_ap(xr1 + br + dr);
            float z = sig_ap(xz1 + bz + dz);
            float n = tanh_ap(fmaf(r, bn + dn, xn1));
            h[1] = n + z * (h[1] - n);
            Bh[bb][jj] = __float2half_rn(h[1]);
        }
        __syncthreads();
    }

    // write final forward h
    {
        int off = net ? 256 : 0;
        d_hcat[(size_t)(b0 + bL) * 512 + off + jj]     = h[0];
        d_hcat[(size_t)(b0 + bL + 4) * 512 + off + jj] = h[1];
    }
}

// ---- backward direction = ONE GRU step from h0=0 on x[:, T-1] --------------
__global__ __launch_bounds__(128) void bwd_kernel(
    const float* __restrict__ g_x, const float* __restrict__ a_x,
    const float* __restrict__ g_wib, const float* __restrict__ g_bib, const float* __restrict__ g_bhb,
    const float* __restrict__ a_wib, const float* __restrict__ a_bib, const float* __restrict__ a_bhb) {
    int b = blockIdx.x;
    int net = blockIdx.y;
    const float* x  = net ? a_x : g_x;
    int I           = net ? 64 : 63;
    const float* Wi = net ? a_wib : g_wib;
    const float* bi = net ? a_bib : g_bib;
    const float* bv = net ? a_bhb : g_bhb;

    __shared__ float xrow[64];
    int u = threadIdx.x;  // 0..127
    if (u < 64) xrow[u] = (u < I) ? x[(size_t)b * T * I + (size_t)(T - 1) * I + u] : 0.0f;
    __syncthreads();

    float s[3];
#pragma unroll
    for (int g = 0; g < 3; g++) {
        const float* wrow = Wi + (size_t)(g * 128 + u) * I;
        float acc = bi[g * 128 + u];
        for (int k = 0; k < I; k++) acc += wrow[k] * xrow[k];
        s[g] = acc;
    }
    float r = sigmoidf_(s[0] + bv[u]);
    float z = sigmoidf_(s[1] + bv[128 + u]);
    float n = tanhf(s[2] + r * bv[256 + u]);
    float hb = (1.0f - z) * n;  // + z*h0, h0 = 0

    int off = net ? 256 : 0;
    d_hcat[(size_t)b * 512 + off + 128 + u] = hb;
}

// ---- fusion MLP (512->256->128 relu) + heads (20, 30) ----------------------
__global__ __launch_bounds__(256) void mlp_kernel(
    const float* __restrict__ w1, const float* __restrict__ b1,
    const float* __restrict__ w2, const float* __restrict__ b2,
    const float* __restrict__ wm, const float* __restrict__ bm,
    const float* __restrict__ wa, const float* __restrict__ ba,
    float* __restrict__ out) {
    int b = blockIdx.x;
    __shared__ float hin[512];
    __shared__ float h1[256];
    __shared__ float h2[128];
    int t = threadIdx.x;
    hin[t]       = d_hcat[(size_t)b * 512 + t];
    hin[t + 256] = d_hcat[(size_t)b * 512 + 256 + t];
    __syncthreads();
    {
        float acc = b1[t];
        const float* wr = w1 + (size_t)t * 512;
#pragma unroll 8
        for (int k = 0; k < 512; k++) acc += wr[k] * hin[k];
        h1[t] = fmaxf(acc, 0.0f);
    }
    __syncthreads();
    if (t < 128) {
        float acc = b2[t];
        const float* wr = w2 + (size_t)t * 256;
#pragma unroll 8
        for (int k = 0; k < 256; k++) acc += wr[k] * h1[k];
        h2[t] = fmaxf(acc, 0.0f);
    }
    __syncthreads();
    if (t < 20) {
        float acc = bm[t];
        const float* wr = wm + (size_t)t * 128;
#pragma unroll 8
        for (int k = 0; k < 128; k++) acc += wr[k] * h2[k];
        out[(size_t)b * 20 + t] = acc;                       // lm
    } else if (t < 50) {
        int q = t - 20;
        float acc = ba[q];
        const float* wr = wa + (size_t)q * 128;
#pragma unroll 8
        for (int k = 0; k < 128; k++) acc += wr[k] * h2[k];
        out[5120 + (size_t)b * 30 + q] = acc;                // la (after 256*20 lm)
    }
}

extern "C" void kernel_launch(void* const* d_in, const int* in_sizes, int n_in,
                              void* d_out, int out_size) {
    const float* g_seq  = (const float*)d_in[0];
    const float* a_seq  = (const float*)d_in[1];
    const float* g_wif  = (const float*)d_in[2];
    const float* g_whf  = (const float*)d_in[3];
    const float* g_bif  = (const float*)d_in[4];
    const float* g_bhf  = (const float*)d_in[5];
    const float* g_wib  = (const float*)d_in[6];
    const float* g_bib  = (const float*)d_in[8];
    const float* g_bhb  = (const float*)d_in[9];
    const float* a_wif  = (const float*)d_in[10];
    const float* a_whf  = (const float*)d_in[11];
    const float* a_bif  = (const float*)d_in[12];
    const float* a_bhf  = (const float*)d_in[13];
    const float* a_wib  = (const float*)d_in[14];
    const float* a_bib  = (const float*)d_in[16];
    const float* a_bhb  = (const float*)d_in[17];
    const float* fuse_w1 = (const float*)d_in[18];
    const float* fuse_b1 = (const float*)d_in[19];
    const float* fuse_w2 = (const float*)d_in[20];
    const float* fuse_b2 = (const float*)d_in[21];
    const float* wm = (const float*)d_in[22];
    const float* bm = (const float*)d_in[23];
    const float* wa = (const float*)d_in[24];
    const float* ba = (const float*)d_in[25];

    static int smem_set = 0;
    if (!smem_set) {
        cudaFuncSetAttribute(proj_kernel, cudaFuncAttributeMaxDynamicSharedMemorySize, 106496);
        smem_set = 1;
    }

    tr_kernel<<<2, 384>>>(g_wif, a_wif);
    proj_kernel<<<dim3(T / 4, B / 32, 2), 384, 106496>>>(g_seq, a_seq, g_bif, a_bif);
    bwd_kernel<<<dim3(B, 2), 128>>>(g_seq, a_seq, g_wib, g_bib, g_bhb, a_wib, a_bib, a_bhb);
    rec_mma_kernel<<<dim3(B / 8, 2), 512>>>(g_whf, g_bhf, a_whf, a_bhf);
    mlp_kernel<<<B, 256>>>(fuse_w1, fuse_b1, fuse_w2, fuse_b2, wm, bm, wa, ba, (float*)d_out);
}

// round 7
// speedup vs baseline: 2.0641x; 1.2792x over previous
#include <cuda_runtime.h>
#include <cuda_bf16.h>
#include <cuda_fp16.h>
#include <cstdint>

// ---------------------------------------------------------------------------
// EarlyFusionGRU: two biGRUs (B=256, T=512, H=128) + fusion MLP + 2 heads.
// Backward direction contributes only hb_seq[0] = ONE GRU step from h0=0 on
// x[:, T-1]. Forward recurrence AND input projection both run on HMMA
// (mma.sync) with fp16 2-term splits for ~fp32 accuracy.
// ---------------------------------------------------------------------------

#define B 256
#define T 512
#define H 128
#define G3 384   // 3*H
typedef unsigned long long ull;

static __device__ float d_pre_g[(size_t)B * T * G3];   // fwd input projections (g net)
static __device__ float d_pre_a[(size_t)B * T * G3];   // fwd input projections (a net)
static __device__ float d_WiT[2][64 * G3];             // transposed+padded fwd input weights
static __device__ float d_hcat[(size_t)B * 512];       // [hg_f | hg_b | ha_f | ha_b]

__device__ __forceinline__ float sigmoidf_(float x) { return 1.0f / (1.0f + expf(-x)); }
__device__ __forceinline__ float tanh_ap(float x) {
    float y; asm("tanh.approx.f32 %0, %1;" : "=f"(y) : "f"(x)); return y;
}
__device__ __forceinline__ float sig_ap(float x) {
    return fmaf(tanh_ap(0.5f * x), 0.5f, 0.5f);
}

__device__ __forceinline__ uint32_t pkh2(float a, float b) {
    __half2 h = __floats2half2_rn(a, b);
    return *(uint32_t*)&h;
}
// split float2 into fp16 hi-pair and fp16 lo-pair
__device__ __forceinline__ void split2(float2 v, uint32_t& hi, uint32_t& lo) {
    float hx = __half2float(__float2half_rn(v.x));
    float hy = __half2float(__float2half_rn(v.y));
    hi = pkh2(hx, hy);
    lo = pkh2(v.x - hx, v.y - hy);
}
__device__ __forceinline__ void mma16816(float* c, const uint32_t* a, uint32_t b0, uint32_t b1) {
    asm volatile(
        "mma.sync.aligned.m16n8k16.row.col.f32.f16.f16.f32 "
        "{%0,%1,%2,%3}, {%4,%5,%6,%7}, {%8,%9}, {%0,%1,%2,%3};"
        : "+f"(c[0]), "+f"(c[1]), "+f"(c[2]), "+f"(c[3])
        : "r"(a[0]), "r"(a[1]), "r"(a[2]), "r"(a[3]), "r"(b0), "r"(b1));
}

// ---- transpose fwd input weights into [k][j] layout, zero-pad k to 64 ------
__global__ void tr_kernel(const float* __restrict__ g_wif, const float* __restrict__ a_wif) {
    int net = blockIdx.x;
    const float* Wi = net ? a_wif : g_wif;
    int I = net ? 64 : 63;
    int j = threadIdx.x;  // 0..383
    for (int k = 0; k < 64; k++)
        d_WiT[net][k * G3 + j] = (k < I) ? Wi[j * I + k] : 0.0f;
}

// ---- input projection on HMMA ----------------------------------------------
// P[n][j] = X[n][64] @ WiT[64][384] + bi,  n = t*B + b (exactly pre's layout).
// A = X (from smem, hi/lo split), B = W (register-resident, hi/lo split).
// 3 split terms: Xhi*Whi + Xlo*Whi + Xhi*Wlo. C cols are j -> coalesced f2 STG.
__global__ __launch_bounds__(384) void proj_mma_kernel(
    const float* __restrict__ g_x, const float* __restrict__ a_x,
    const float* __restrict__ g_bi, const float* __restrict__ a_bi) {
    int net = blockIdx.y;
    int n0 = blockIdx.x * 128;
    const float* x = net ? a_x : g_x;
    int I = net ? 64 : 63;
    float* pre = net ? d_pre_a : d_pre_g;
    const float* bi = net ? a_bi : g_bi;

    __shared__ __half Xh[128][72];   // X hi halves, padded pitch (conflict-free)
    __shared__ __half Xl[128][72];   // X lo halves

    int tid = threadIdx.x;
    int wid = tid >> 5, lane = tid & 31;
    int qr = lane >> 2, qc = lane & 3;
    int J = wid * 32;                // this warp's 32 j-columns

    // B-fragments (W), persistent: Bf[jt][ks][reg], hi and lo terms
    uint32_t Bh_[4][4][2], Bl_[4][4][2];
    {
        const float* wt = d_WiT[net];
#pragma unroll
        for (int jt = 0; jt < 4; jt++) {
            int j = J + jt * 8 + qr;
#pragma unroll
            for (int ks = 0; ks < 4; ks++) {
#pragma unroll
                for (int r = 0; r < 2; r++) {
                    int k = ks * 16 + qc * 2 + r * 8;
                    float w0 = wt[k * G3 + j];
                    float w1 = wt[(k + 1) * G3 + j];
                    split2(make_float2(w0, w1), Bh_[jt][ks][r], Bl_[jt][ks][r]);
                }
            }
        }
    }
    // biases for this thread's output columns
    float bj0[4], bj1[4];
#pragma unroll
    for (int jt = 0; jt < 4; jt++) {
        bj0[jt] = bi[J + jt * 8 + 2 * qc];
        bj1[jt] = bi[J + jt * 8 + 2 * qc + 1];
    }

    // load X tile [128][64] -> split into Xh/Xl
    for (int idx = tid; idx < 128 * 64; idx += 384) {
        int r = idx >> 6, k = idx & 63;
        int n = n0 + r;
        int t = n >> 8, b = n & 255;
        float v = (k < I) ? x[((size_t)b * T + t) * I + k] : 0.0f;
        __half hv = __float2half_rn(v);
        Xh[r][k] = hv;
        Xl[r][k] = __float2half_rn(v - __half2float(hv));
    }
    __syncthreads();

#pragma unroll 1
    for (int mt = 0; mt < 8; mt++) {
        float c[4][4];
#pragma unroll
        for (int jt = 0; jt < 4; jt++) {
            c[jt][0] = bj0[jt]; c[jt][1] = bj1[jt];
            c[jt][2] = bj0[jt]; c[jt][3] = bj1[jt];
        }
#pragma unroll
        for (int ks = 0; ks < 4; ks++) {
            int row = mt * 16 + qr;
            const __half* ph = &Xh[row][ks * 16 + qc * 2];
            const __half* pl = &Xl[row][ks * 16 + qc * 2];
            uint32_t Ah[4], Al[4];
            Ah[0] = *(const uint32_t*)ph;
            Ah[1] = *(const uint32_t*)(ph + 8 * 72);
            Ah[2] = *(const uint32_t*)(ph + 8);
            Ah[3] = *(const uint32_t*)(ph + 8 * 72 + 8);
            Al[0] = *(const uint32_t*)pl;
            Al[1] = *(const uint32_t*)(pl + 8 * 72);
            Al[2] = *(const uint32_t*)(pl + 8);
            Al[3] = *(const uint32_t*)(pl + 8 * 72 + 8);
#pragma unroll
            for (int jt = 0; jt < 4; jt++) {
                mma16816(c[jt], Ah, Bh_[jt][ks][0], Bh_[jt][ks][1]);
                mma16816(c[jt], Al, Bh_[jt][ks][0], Bh_[jt][ks][1]);
                mma16816(c[jt], Ah, Bl_[jt][ks][0], Bl_[jt][ks][1]);
            }
        }
        // store: rows n0+mt*16+qr (+8), cols J+jt*8+2qc (+1) -> float2
#pragma unroll
        for (int jt = 0; jt < 4; jt++) {
            int j0 = J + jt * 8 + 2 * qc;
            float* p0 = pre + (size_t)(n0 + mt * 16 + qr) * G3 + j0;
            *(float2*)p0 = make_float2(c[jt][0], c[jt][1]);
            *(float2*)(p0 + (size_t)8 * G3) = make_float2(c[jt][2], c[jt][3]);
        }
    }
}

// ---- forward GRU recurrence on HMMA (mma.sync), split terms across warps ---
// Per step: D[384,8] = Whi@h16 + Wlo@h16. 16 warps: warp = (mgroup 0-7,
// khalf 0/1); khalf selects the split term; 8-deep k chains. x-parts for
// step t+1 prefetched during step t's MMA phase (hides DRAM latency).
__global__ __launch_bounds__(512, 1) void rec_mma_kernel(
    const float* __restrict__ g_wh, const float* __restrict__ g_bh,
    const float* __restrict__ a_wh, const float* __restrict__ a_bh) {
    int net = blockIdx.y;
    int b0 = blockIdx.x * 8;
    const float* pre = net ? d_pre_a : d_pre_g;
    const float* Wh  = net ? a_wh : g_wh;
    const float* bh  = net ? a_bh : g_bh;

    int tid = threadIdx.x;
    int wid = tid >> 5;
    int lane = tid & 31;
    int qr = lane >> 2;
    int qc = lane & 3;
    int mgroup = wid >> 1;  // 0..7 -> rows [mgroup*48, +48)
    int khalf = wid & 1;    // 0 = hi term, 1 = lo term

    __shared__ __half Bh[8][136];         // [n(batch)][k(hidden)], padded
    __shared__ float  Dsh[2][384][10];    // per-term gate pre-activations

    // register-resident A fragments: this warp's term only
    uint32_t A[3][8][4];
#pragma unroll
    for (int mt = 0; mt < 3; mt++) {
        int R = (mgroup * 3 + mt) * 16;
        int r0 = R + qr, r1 = r0 + 8;
        const float2* w0p = (const float2*)(Wh + (size_t)r0 * 128);
        const float2* w1p = (const float2*)(Wh + (size_t)r1 * 128);
#pragma unroll
        for (int kb = 0; kb < 8; kb++) {
            int ci = kb * 8 + qc;
            float2 e00 = w0p[ci], e10 = w1p[ci];
            float2 e01 = w0p[ci + 4], e11 = w1p[ci + 4];
            uint32_t hi, lo;
            split2(e00, hi, lo); A[mt][kb][0] = khalf ? lo : hi;
            split2(e10, hi, lo); A[mt][kb][1] = khalf ? lo : hi;
            split2(e01, hi, lo); A[mt][kb][2] = khalf ? lo : hi;
            split2(e11, hi, lo); A[mt][kb][3] = khalf ? lo : hi;
        }
    }

    // zero B tile (h0 = 0)
    for (int i = tid; i < 8 * 136 / 2; i += 512)
        ((uint32_t*)Bh)[i] = 0u;

    // activation bookkeeping: thread owns (bL, jj) and (bL+4, jj)
    int bL = tid >> 7;            // 0..3
    int jj = tid & 127;
    float br = bh[jj], bz = bh[128 + jj], bn = bh[256 + jj];
    const float* xb0 = pre + (size_t)(b0 + bL) * G3 + jj;
    const float* xb1 = xb0 + 4 * G3;

    float h0v = 0.0f, h1v = 0.0f;

    // prefetch x-parts for t = 0
    float xr0 = xb0[0], xz0 = xb0[128], xn0 = xb0[256];
    float xr1 = xb1[0], xz1 = xb1[128], xn1 = xb1[256];

    const __half* BhF = &Bh[0][0];
    __syncthreads();

#pragma unroll 1
    for (int t = 0; t < T; t++) {
        // prefetch x-parts for step t+1 (covered by this step's MMA+act)
        float pr0 = 0.f, pz0 = 0.f, pn0 = 0.f, pr1 = 0.f, pz1 = 0.f, pn1 = 0.f;
        if (t + 1 < T) {
            const float* q0 = xb0 + (size_t)(t + 1) * (B * G3);
            const float* q1 = xb1 + (size_t)(t + 1) * (B * G3);
            pr0 = q0[0]; pz0 = q0[128]; pn0 = q0[256];
            pr1 = q1[0]; pz1 = q1[128]; pn1 = q1[256];
        }

        // MMA phase: this warp's term, 8-deep chain
        float c[3][4];
#pragma unroll
        for (int mt = 0; mt < 3; mt++) { c[mt][0] = c[mt][1] = c[mt][2] = c[mt][3] = 0.0f; }
#pragma unroll
        for (int kb = 0; kb < 8; kb++) {
            int koff = qr * 136 + kb * 16 + qc * 2;
            uint32_t bf0 = *(const uint32_t*)(BhF + koff);
            uint32_t bf1 = *(const uint32_t*)(BhF + koff + 8);
#pragma unroll
            for (int mt = 0; mt < 3; mt++) mma16816(c[mt], A[mt][kb], bf0, bf1);
        }
#pragma unroll
        for (int mt = 0; mt < 3; mt++) {
            int R = (mgroup * 3 + mt) * 16;
            *(float2*)&Dsh[khalf][R + qr][2 * qc]     = make_float2(c[mt][0], c[mt][1]);
            *(float2*)&Dsh[khalf][R + qr + 8][2 * qc] = make_float2(c[mt][2], c[mt][3]);
        }
        __syncthreads();

        // activation phase: 2 (batch, jj) entries per thread
        {
            int bb = bL;
            float dr = Dsh[0][jj][bb]       + Dsh[1][jj][bb];
            float dz = Dsh[0][jj + 128][bb] + Dsh[1][jj + 128][bb];
            float dn = Dsh[0][jj + 256][bb] + Dsh[1][jj + 256][bb];
            float r = sig_ap(xr0 + br + dr);
            float z = sig_ap(xz0 + bz + dz);
            float n = tanh_ap(fmaf(r, bn + dn, xn0));
            h0v = n + z * (h0v - n);
            Bh[bb][jj] = __float2half_rn(h0v);
        }
        {
            int bb = bL + 4;
            float dr = Dsh[0][jj][bb]       + Dsh[1][jj][bb];
            float dz = Dsh[0][jj + 128][bb] + Dsh[1][jj + 128][bb];
            float dn = Dsh[0][jj + 256][bb] + Dsh[1][jj + 256][bb];
            float r = sig_ap(xr1 + br + dr);
            float z = sig_ap(xz1 + bz + dz);
            float n = tanh_ap(fmaf(r, bn + dn, xn1));
            h1v = n + z * (h1v - n);
            Bh[bb][jj] = __float2half_rn(h1v);
        }
        __syncthreads();

        xr0 = pr0; xz0 = pz0; xn0 = pn0;
        xr1 = pr1; xz1 = pz1; xn1 = pn1;
    }

    // write final forward h
    {
        int off = net ? 256 : 0;
        d_hcat[(size_t)(b0 + bL) * 512 + off + jj]     = h0v;
        d_hcat[(size_t)(b0 + bL + 4) * 512 + off + jj] = h1v;
    }
}

// ---- backward direction = ONE GRU step from h0=0 on x[:, T-1] --------------
__global__ __launch_bounds__(128) void bwd_kernel(
    const float* __restrict__ g_x, const float* __restrict__ a_x,
    const float* __restrict__ g_wib, const float* __restrict__ g_bib, const float* __restrict__ g_bhb,
    const float* __restrict__ a_wib, const float* __restrict__ a_bib, const float* __restrict__ a_bhb) {
    int b = blockIdx.x;
    int net = blockIdx.y;
    const float* x  = net ? a_x : g_x;
    int I           = net ? 64 : 63;
    const float* Wi = net ? a_wib : g_wib;
    const float* bi = net ? a_bib : g_bib;
    const float* bv = net ? a_bhb : g_bhb;

    __shared__ float xrow[64];
    int u = threadIdx.x;  // 0..127
    if (u < 64) xrow[u] = (u < I) ? x[(size_t)b * T * I + (size_t)(T - 1) * I + u] : 0.0f;
    __syncthreads();

    float s[3];
#pragma unroll
    for (int g = 0; g < 3; g++) {
        const float* wrow = Wi + (size_t)(g * 128 + u) * I;
        float acc = bi[g * 128 + u];
        for (int k = 0; k < I; k++) acc += wrow[k] * xrow[k];
        s[g] = acc;
    }
    float r = sigmoidf_(s[0] + bv[u]);
    float z = sigmoidf_(s[1] + bv[128 + u]);
    float n = tanhf(s[2] + r * bv[256 + u]);
    float hb = (1.0f - z) * n;  // + z*h0, h0 = 0

    int off = net ? 256 : 0;
    d_hcat[(size_t)b * 512 + off + 128 + u] = hb;
}

// ---- fusion MLP (512->256->128 relu) + heads (20, 30) ----------------------
__global__ __launch_bounds__(256) void mlp_kernel(
    const float* __restrict__ w1, const float* __restrict__ b1,
    const float* __restrict__ w2, const float* __restrict__ b2,
    const float* __restrict__ wm, const float* __restrict__ bm,
    const float* __restrict__ wa, const float* __restrict__ ba,
    float* __restrict__ out) {
    int b = blockIdx.x;
    __shared__ float hin[512];
    __shared__ float h1[256];
    __shared__ float h2[128];
    int t = threadIdx.x;
    hin[t]       = d_hcat[(size_t)b * 512 + t];
    hin[t + 256] = d_hcat[(size_t)b * 512 + 256 + t];
    __syncthreads();
    {
        float acc = b1[t];
        const float* wr = w1 + (size_t)t * 512;
#pragma unroll 8
        for (int k = 0; k < 512; k++) acc += wr[k] * hin[k];
        h1[t] = fmaxf(acc, 0.0f);
    }
    __syncthreads();
    if (t < 128) {
        float acc = b2[t];
        const float* wr = w2 + (size_t)t * 256;
#pragma unroll 8
        for (int k = 0; k < 256; k++) acc += wr[k] * h1[k];
        h2[t] = fmaxf(acc, 0.0f);
    }
    __syncthreads();
    if (t < 20) {
        float acc = bm[t];
        const float* wr = wm + (size_t)t * 128;
#pragma unroll 8
        for (int k = 0; k < 128; k++) acc += wr[k] * h2[k];
        out[(size_t)b * 20 + t] = acc;                       // lm
    } else if (t < 50) {
        int q = t - 20;
        float acc = ba[q];
        const float* wr = wa + (size_t)q * 128;
#pragma unroll 8
        for (int k = 0; k < 128; k++) acc += wr[k] * h2[k];
        out[5120 + (size_t)b * 30 + q] = acc;                // la (after 256*20 lm)
    }
}

extern "C" void kernel_launch(void* const* d_in, const int* in_sizes, int n_in,
                              void* d_out, int out_size) {
    const float* g_seq  = (const float*)d_in[0];
    const float* a_seq  = (const float*)d_in[1];
    const float* g_wif  = (const float*)d_in[2];
    const float* g_whf  = (const float*)d_in[3];
    const float* g_bif  = (const float*)d_in[4];
    const float* g_bhf  = (const float*)d_in[5];
    const float* g_wib  = (const float*)d_in[6];
    const float* g_bib  = (const float*)d_in[8];
    const float* g_bhb  = (const float*)d_in[9];
    const float* a_wif  = (const float*)d_in[10];
    const float* a_whf  = (const float*)d_in[11];
    const float* a_bif  = (const float*)d_in[12];
    const float* a_bhf  = (const float*)d_in[13];
    const float* a_wib  = (const float*)d_in[14];
    const float* a_bib  = (const float*)d_in[16];
    const float* a_bhb  = (const float*)d_in[17];
    const float* fuse_w1 = (const float*)d_in[18];
    const float* fuse_b1 = (const float*)d_in[19];
    const float* fuse_w2 = (const float*)d_in[20];
    const float* fuse_b2 = (const float*)d_in[21];
    const float* wm = (const float*)d_in[22];
    const float* bm = (const float*)d_in[23];
    const float* wa = (const float*)d_in[24];
    const float* ba = (const float*)d_in[25];

    tr_kernel<<<2, 384>>>(g_wif, a_wif);
    proj_mma_kernel<<<dim3((T * B) / 128, 2), 384>>>(g_seq, a_seq, g_bif, a_bif);
    bwd_kernel<<<dim3(B, 2), 128>>>(g_seq, a_seq, g_wib, g_bib, g_bhb, a_wib, a_bib, a_bhb);
    rec_mma_kernel<<<dim3(B / 8, 2), 512>>>(g_whf, g_bhf, a_whf, a_bhf);
    mlp_kernel<<<B, 256>>>(fuse_w1, fuse_b1, fuse_w2, fuse_b2, wm, bm, wa, ba, (float*)d_out);
}